// round 15
// baseline (speedup 1.0000x reference)
#include <cuda_runtime.h>
#include <math.h>
#include <stdint.h>

#define Bn 4
#define Cn 32
#define N0 (4*32*256*256)
#define N1 (4*32*128*128)
#define N2 (4*32*64*64)

typedef unsigned long long ull;

__device__ __forceinline__ ull pack2(float lo, float hi) {
    ull d;
    asm("mov.b64 %0, {%1, %2};" : "=l"(d) : "f"(lo), "f"(hi));
    return d;
}
__device__ __forceinline__ float2 unpack2(ull v) {
    float2 f;
    asm("mov.b64 {%0, %1}, %2;" : "=f"(f.x), "=f"(f.y) : "l"(v));
    return f;
}
__device__ __forceinline__ ull ffma2(ull a, ull b, ull c) {
    ull d;
    asm("fma.rn.f32x2 %0, %1, %2, %3;" : "=l"(d) : "l"(a), "l"(b), "l"(c));
    return d;
}

// ---------------- device scratch ----------------
__device__ float g_z0[N0];   // CHW
__device__ float g_q [N0];   // CHW
__device__ float g_z1[N1];   // HWC
__device__ float g_z2[N2];   // HWC
__device__ float g_y1[N0];   // CHW
__device__ float g_y2[N0];   // CHW
__device__ float g_o12a[12*4*65536];   // head1 offsets/logits, 12 planes
__device__ float g_o12b[12*4*65536];   // head2
__device__ float g_pz0[4*256*32];
__device__ float g_py1[4*128*32];
__device__ float g_py2[4*128*32];
__device__ float g_alpha[12];
__device__ int   g_ctr = 0;

// ---------------- fused (inline-pool) + dwconv3(f32x2) + pw1x1(f32x2) + BN + SiLU (+ q-proj + partials) ----------------
template<int H, int W, int F, bool FUSEQ, bool HWC>
__device__ __forceinline__ void ds_impl(float* smem,
                          const float* __restrict__ x,
                          const float* __restrict__ dw,
                          const float* __restrict__ pw,
                          const float* __restrict__ gg,
                          const float* __restrict__ bb,
                          const float* __restrict__ mm,
                          const float* __restrict__ vv,
                          const float* __restrict__ qw,
                          float* __restrict__ z, float* __restrict__ q,
                          float* __restrict__ pz,
                          int bxi, int byi, int b, int blkLocal)
{
    float* s_tile = smem;            // 10368, pair-interleaved [cp][y][x][2]
    float* s_dw   = smem + 10368;    // 288
    int tid = threadIdx.x;
    int tx = tid & 15, ty = tid >> 4;
    int bx = bxi * 16, by = byi * 16;
    const float* xb = x + b*Cn*256*256;

    for (int i = tid; i < 32*324; i += 256) {
        int c = i / 324; int r = i % 324; int yy = r/18, xx = r%18;
        int gy = by + yy - 1, gx = bx + xx - 1;
        float val = 0.f;
        if (gy >= 0 && gy < H && gx >= 0 && gx < W) {
            if (F == 1) {
                val = xb[(c*256+gy)*256 + gx];
            } else if (F == 2) {
                const float2* p = (const float2*)(xb + (c*256 + 2*gy)*256 + 2*gx);
                float2 a = p[0], bq = p[128];
                val = 0.25f*(a.x + a.y + bq.x + bq.y);
            } else {
                const float4* p = (const float4*)(xb + (c*256 + 4*gy)*256 + 4*gx);
                float s = 0.f;
                #pragma unroll
                for (int fy = 0; fy < 4; fy++) {
                    float4 v4 = p[fy*64];
                    s += v4.x + v4.y + v4.z + v4.w;
                }
                val = s * 0.0625f;
            }
        }
        s_tile[((c >> 1)*324 + r)*2 + (c & 1)] = val;
    }
    for (int i = tid; i < 288; i += 256) {
        int c = i / 9, k = i % 9;
        s_dw[((c >> 1)*9 + k)*2 + (c & 1)] = dw[i];
    }
    __syncthreads();

    float t[32];
    #pragma unroll
    for (int cp = 0; cp < 16; cp++) {
        const float* tp = s_tile + (cp*324 + ty*18 + tx)*2;
        const float* wp = s_dw + cp*18;
        ull a2 = 0ull;
        #pragma unroll
        for (int ky = 0; ky < 3; ky++)
            #pragma unroll
            for (int kx = 0; kx < 3; kx++) {
                ull v2 = *(const ull*)(tp + (ky*18+kx)*2);
                ull w2 = *(const ull*)(wp + (ky*3+kx)*2);
                a2 = ffma2(v2, w2, a2);
            }
        float2 f = unpack2(a2);
        t[2*cp] = f.x; t[2*cp+1] = f.y;
    }
    __syncthreads();

    float* s_pwT = smem;             // [c][o], stride 36 (16B aligned)
    float* s_qwT = smem + 1152;
    float* s_sc  = smem + 2304;
    float* s_bi  = smem + 2336;
    for (int i = tid; i < 1024; i += 256) s_pwT[(i & 31)*36 + (i >> 5)] = pw[i];
    if (FUSEQ) for (int i = tid; i < 1024; i += 256) s_qwT[(i & 31)*36 + (i >> 5)] = qw[i];
    if (tid < 32) {
        float sc = gg[tid] * rsqrtf(vv[tid] + 1e-5f);
        s_sc[tid] = sc; s_bi[tid] = bb[tid] - mm[tid]*sc;
    }
    __syncthreads();

    int gy = by + ty, gx = bx + tx;
    float zl[32];
    {
        ull acc2[16];
        #pragma unroll
        for (int op = 0; op < 16; op++) acc2[op] = 0ull;
        #pragma unroll
        for (int c = 0; c < 32; c++) {
            ull m2 = pack2(t[c], t[c]);
            const float4* w4 = (const float4*)(s_pwT + c*36);
            #pragma unroll
            for (int oq = 0; oq < 8; oq++) {
                float4 w = w4[oq];
                const ull* wp = (const ull*)&w;
                acc2[oq*2+0] = ffma2(m2, wp[0], acc2[oq*2+0]);
                acc2[oq*2+1] = ffma2(m2, wp[1], acc2[oq*2+1]);
            }
        }
        #pragma unroll
        for (int op = 0; op < 16; op++) {
            float2 f = unpack2(acc2[op]);
            int o0 = 2*op, o1 = 2*op+1;
            float v0 = f.x*s_sc[o0] + s_bi[o0];
            float v1 = f.y*s_sc[o1] + s_bi[o1];
            zl[o0] = v0 / (1.f + __expf(-v0));
            zl[o1] = v1 / (1.f + __expf(-v1));
        }
    }
    if (HWC) {
        float4* zp4 = (float4*)(z + ((size_t)(b*H + gy)*W + gx)*32);
        #pragma unroll
        for (int j = 0; j < 8; j++)
            zp4[j] = make_float4(zl[4*j], zl[4*j+1], zl[4*j+2], zl[4*j+3]);
    } else {
        float* zp = z + ((size_t)b*Cn*H + gy)*W + gx;
        #pragma unroll
        for (int o = 0; o < 32; o++) zp[o*H*W] = zl[o];
    }
    if (FUSEQ) {
        float* qp = q + ((size_t)b*Cn*H + gy)*W + gx;
        #pragma unroll
        for (int half = 0; half < 2; half++) {
            ull acc2[8];
            #pragma unroll
            for (int op = 0; op < 8; op++) acc2[op] = 0ull;
            #pragma unroll
            for (int c = 0; c < 32; c++) {
                ull m2 = pack2(zl[c], zl[c]);
                const float4* w4 = (const float4*)(s_qwT + c*36) + half*4;
                #pragma unroll
                for (int oq = 0; oq < 4; oq++) {
                    float4 w = w4[oq];
                    const ull* wp = (const ull*)&w;
                    acc2[oq*2+0] = ffma2(m2, wp[0], acc2[oq*2+0]);
                    acc2[oq*2+1] = ffma2(m2, wp[1], acc2[oq*2+1]);
                }
            }
            #pragma unroll
            for (int op = 0; op < 8; op++) {
                float2 f = unpack2(acc2[op]);
                qp[(half*16 + 2*op)*H*W]   = f.x;
                qp[(half*16 + 2*op+1)*H*W] = f.y;
            }
        }
        __syncthreads();
        float* s_red = smem;
        int lane = tid & 31, wid = tid >> 5;
        #pragma unroll
        for (int c = 0; c < 32; c++) {
            float v = zl[c];
            v += __shfl_down_sync(0xffffffffu, v, 16);
            v += __shfl_down_sync(0xffffffffu, v, 8);
            v += __shfl_down_sync(0xffffffffu, v, 4);
            v += __shfl_down_sync(0xffffffffu, v, 2);
            v += __shfl_down_sync(0xffffffffu, v, 1);
            if (lane == 0) s_red[c*8 + wid] = v;
        }
        __syncthreads();
        if (tid < 32) {
            float s = 0.f;
            #pragma unroll
            for (int w = 0; w < 8; w++) s += s_red[tid*8 + w];
            pz[(b*256 + blkLocal)*32 + tid] = s;
        }
    }
}

__global__ void __launch_bounds__(256, 3) ds_fat_kernel(
    const float* __restrict__ x,
    const float* d0dw, const float* d0pw, const float* d0g, const float* d0b, const float* d0m, const float* d0v,
    const float* d1dw, const float* d1pw, const float* d1g, const float* d1b, const float* d1m, const float* d1v,
    const float* d2dw, const float* d2pw, const float* d2g, const float* d2b, const float* d2m, const float* d2v,
    const float* qw, float* z0, float* q, float* z1, float* z2, float* pz0)
{
    __shared__ __align__(16) float smem[10688];
    int bid = blockIdx.x;
    if (bid < 256) {
        ds_impl<128,128,2,false,true>(smem, x, d1dw, d1pw, d1g, d1b, d1m, d1v, nullptr, z1, nullptr, nullptr,
                                      bid & 7, (bid >> 3) & 7, bid >> 6, 0);
    } else if (bid < 320) {
        int r = bid - 256;
        ds_impl<64,64,4,false,true>(smem, x, d2dw, d2pw, d2g, d2b, d2m, d2v, nullptr, z2, nullptr, nullptr,
                                    r & 3, (r >> 2) & 3, r >> 4, 0);
    } else {
        int r = bid - 320;
        ds_impl<256,256,1,true,false>(smem, x, d0dw, d0pw, d0g, d0b, d0m, d0v, qw, z0, q, pz0,
                                      r & 15, (r >> 4) & 15, r >> 8, r & 255);
    }
}

// ---------------- conv head: conv3x3(f32x2) + SiLU + conv1x1 -> o12 planes ----------------
// smem: tile 8ch x 10 x 68 = 5440 | w1T 1152 | w2 192 | b2 16 = 6800 floats
__device__ __forceinline__ void conv_head_impl(float* smem,
                            const float* __restrict__ q,
                            const float* __restrict__ w1,
                            const float* __restrict__ w2,
                            const float* __restrict__ b2,
                            float* __restrict__ o12p,   // 12 planes of [4][256][256]
                            int bxi, int byi, int b)
{
    float* s_tile = smem;            // 5440
    float* s_w1   = smem + 5440;     // 1152
    float* s_w2   = s_w1 + 1152;     // 192
    float* s_b2   = s_w2 + 192;      // 16
    int tid = threadIdx.x;
    int tx = tid & 63;
    int tyq = tid >> 6;
    int bx = bxi*64, by = byi*8;
    int r0 = tyq*2;

    if (tid < 192) s_w2[tid] = w2[tid];
    if (tid >= 192 && tid < 204) s_b2[tid-192] = b2[tid-192];

    const float* qb = q + (size_t)b*32*65536;

    ull acc2[8][2];
    #pragma unroll
    for (int op = 0; op < 8; op++) { acc2[op][0] = 0ull; acc2[op][1] = 0ull; }

    for (int g = 0; g < 4; g++) {
        __syncthreads();
        for (int i = tid; i < 8*10*66; i += 256) {
            int c = i / 660; int r = i % 660; int yy = r/66, xx = r%66;
            int gy = by + yy - 1, gx = bx + xx - 1;
            float val = 0.f;
            if ((unsigned)gy < 256u && (unsigned)gx < 256u)
                val = qb[((g*8+c)*256 + gy)*256 + gx];
            s_tile[(c*10 + yy)*68 + xx] = val;
        }
        for (int i = tid; i < 1152; i += 256) {
            int cl = i / 144; int rem = i % 144; int kk = rem >> 4; int o = rem & 15;
            s_w1[i] = w1[(o*32 + g*8 + cl)*9 + kk];
        }
        __syncthreads();

        #pragma unroll
        for (int cl = 0; cl < 8; cl++) {
            float v[4][3];
            const float* tp = s_tile + cl*680 + r0*68 + tx;
            #pragma unroll
            for (int rr = 0; rr < 4; rr++)
                #pragma unroll
                for (int cc = 0; cc < 3; cc++) v[rr][cc] = tp[rr*68 + cc];
            ull vd[4][3];
            #pragma unroll
            for (int rr = 0; rr < 4; rr++)
                #pragma unroll
                for (int cc = 0; cc < 3; cc++) vd[rr][cc] = pack2(v[rr][cc], v[rr][cc]);
            const float* wbase = s_w1 + cl*144;
            #pragma unroll
            for (int ky = 0; ky < 3; ky++)
                #pragma unroll
                for (int kx = 0; kx < 3; kx++) {
                    int kk = ky*3 + kx;
                    #pragma unroll
                    for (int oq = 0; oq < 4; oq++) {
                        float4 w4 = *(const float4*)(wbase + kk*16 + oq*4);
                        const ull* wp = (const ull*)&w4;
                        #pragma unroll
                        for (int r = 0; r < 2; r++) {
                            acc2[oq*2+0][r] = ffma2(wp[0], vd[r+ky][kx], acc2[oq*2+0][r]);
                            acc2[oq*2+1][r] = ffma2(wp[1], vd[r+ky][kx], acc2[oq*2+1][r]);
                        }
                    }
                }
        }
    }

    float h[2][16];
    #pragma unroll
    for (int op = 0; op < 8; op++)
        #pragma unroll
        for (int r = 0; r < 2; r++) {
            float2 f = unpack2(acc2[op][r]);
            h[r][2*op]   = f.x / (1.f + __expf(-f.x));
            h[r][2*op+1] = f.y / (1.f + __expf(-f.y));
        }

    int gx = bx + tx;
    #pragma unroll
    for (int r = 0; r < 2; r++) {
        int gy = by + r0 + r;
        size_t pidx = (size_t)b*65536 + gy*256 + gx;
        #pragma unroll
        for (int j = 0; j < 12; j++) {
            float a = s_b2[j];
            #pragma unroll
            for (int i = 0; i < 16; i++) a += s_w2[j*16+i]*h[r][i];
            o12p[(size_t)j*262144 + pidx] = a;
        }
    }
}

__global__ void __launch_bounds__(256, 3) conv_head_kernel(
    const float* __restrict__ q,
    const float* h1w1, const float* h1w2, const float* h1b2,
    const float* h2w1, const float* h2w2, const float* h2b2,
    float* o12a, float* o12b)
{
    __shared__ __align__(16) float smem[6800];
    int hb = blockIdx.x;
    if (hb < 512) {
        int local = hb & 127;
        conv_head_impl(smem, q, h1w1, h1w2, h1b2, o12a, local & 3, local >> 2, hb >> 7);
    } else {
        int r = hb - 512;
        int local = r & 127;
        conv_head_impl(smem, q, h2w1, h2w2, h2b2, o12b, local & 3, local >> 2, r >> 7);
    }
}

// ---------------- gather head: o12 -> tanh/softmax -> smem-window bilinear -> y + partials ----------------
// smem: window WX*WY*8 (<=3200) | cs 256 -> <=3456 floats
template<int Hc, int Wc, int WX, int WY>
__device__ __forceinline__ void gather_head_impl(float* smem,
                            const float* __restrict__ zc,     // HWC
                            const float* __restrict__ o12p,
                            float* __restrict__ y,            // CHW
                            float* __restrict__ py,
                            int bxi, int byi, int b, int blkLocal)
{
    float* s_win = smem;
    float* s_cs  = smem + 3200;   // 256
    int tid = threadIdx.x;
    int tx = tid & 63;
    int tyq = tid >> 6;
    int bx = bxi*64, by = byi*8;
    int r0 = tyq*2;
    int lane = tid & 31, wid = tid >> 5;

    s_cs[tid] = 0.f;

    int gx = bx + tx;
    float xc = (gx + 0.5f)*((float)Wc/256.f) - 0.5f;

    // load o12, compute sampling params
    float swk[2][4], six[2][4], siy[2][4];
    #pragma unroll
    for (int r = 0; r < 2; r++) {
        int gy = by + r0 + r;
        size_t pidx = (size_t)b*65536 + gy*256 + gx;
        float op[12];
        #pragma unroll
        for (int j = 0; j < 12; j++) op[j] = o12p[(size_t)j*262144 + pidx];
        float ycf = (gy + 0.5f)*((float)Hc/256.f) - 0.5f;
        float mlog = fmaxf(fmaxf(op[8],op[9]), fmaxf(op[10],op[11]));
        float e[4]; float es = 0.f;
        #pragma unroll
        for (int k = 0; k < 4; k++) { e[k] = __expf(op[8+k]-mlog); es += e[k]; }
        float inv = 1.f/es;
        #pragma unroll
        for (int k = 0; k < 4; k++) {
            swk[r][k] = e[k]*inv;
            float ix = xc + 2.0f*tanhf(op[2*k]);
            float iy = ycf + 2.0f*tanhf(op[2*k+1]);
            six[r][k] = fminf(fmaxf(ix, 0.f), (float)(Wc-1));
            siy[r][k] = fminf(fmaxf(iy, 0.f), (float)(Hc-1));
        }
    }

    int cx0 = (bx*Wc >> 8) - 3;
    int cy0 = (by*Hc >> 8) - 3;
    const float4* zb4 = (const float4*)(zc + (size_t)b*Hc*Wc*32);

    for (int qtr = 0; qtr < 4; qtr++) {
        __syncthreads();
        for (int i = tid; i < WX*WY*2; i += 256) {
            int cell = i >> 1, j = i & 1;
            int wy = cell / WX, wx = cell - wy*WX;
            int gyc = min(max(cy0 + wy, 0), Hc-1);
            int gxc = min(max(cx0 + wx, 0), Wc-1);
            ((float4*)s_win)[i] = __ldg(zb4 + (size_t)(gyc*Wc + gxc)*8 + qtr*2 + j);
        }
        __syncthreads();
        const float4* w4 = (const float4*)s_win;

        #pragma unroll
        for (int r = 0; r < 2; r++) {
            int gy = by + r0 + r;
            ull yac2[4];
            #pragma unroll
            for (int v = 0; v < 4; v++) yac2[v] = 0ull;
            #pragma unroll
            for (int k = 0; k < 4; k++) {
                float wk = swk[r][k];
                float ix = six[r][k], iy = siy[r][k];
                float x0 = floorf(ix), y0 = floorf(iy);
                float wxr = ix-x0, wyr = iy-y0;
                int x0i = (int)x0, y0i = (int)y0;
                int x1i = min(x0i+1, Wc-1), y1i = min(y0i+1, Hc-1);
                float w00 = wk*(1.f-wxr)*(1.f-wyr), w01 = wk*wxr*(1.f-wyr);
                float w10 = wk*(1.f-wxr)*wyr,       w11 = wk*wxr*wyr;
                ull W00 = pack2(w00,w00), W01 = pack2(w01,w01);
                ull W10 = pack2(w10,w10), W11 = pack2(w11,w11);
                int lx0 = x0i - cx0, lx1 = x1i - cx0;
                int ly0 = y0i - cy0, ly1 = y1i - cy0;
                int i00 = (ly0*WX + lx0)*2, i01 = (ly0*WX + lx1)*2;
                int i10 = (ly1*WX + lx0)*2, i11 = (ly1*WX + lx1)*2;
                #pragma unroll
                for (int v = 0; v < 2; v++) {
                    float4 a00 = w4[i00 + v];
                    float4 a01 = w4[i01 + v];
                    float4 a10 = w4[i10 + v];
                    float4 a11 = w4[i11 + v];
                    const ull* p00 = (const ull*)&a00;
                    const ull* p01 = (const ull*)&a01;
                    const ull* p10 = (const ull*)&a10;
                    const ull* p11 = (const ull*)&a11;
                    #pragma unroll
                    for (int hh = 0; hh < 2; hh++) {
                        ull acc = yac2[v*2+hh];
                        acc = ffma2(W00, p00[hh], acc);
                        acc = ffma2(W01, p01[hh], acc);
                        acc = ffma2(W10, p10[hh], acc);
                        acc = ffma2(W11, p11[hh], acc);
                        yac2[v*2+hh] = acc;
                    }
                }
            }
            float* yp = y + (((size_t)b*32 + qtr*8)*256 + gy)*256 + gx;
            const float* yf = (const float*)yac2;
            #pragma unroll
            for (int c = 0; c < 8; c++) yp[c*65536] = yf[c];
            #pragma unroll
            for (int c = 0; c < 8; c++) {
                float v = yf[c];
                v += __shfl_down_sync(0xffffffffu, v, 16);
                v += __shfl_down_sync(0xffffffffu, v, 8);
                v += __shfl_down_sync(0xffffffffu, v, 4);
                v += __shfl_down_sync(0xffffffffu, v, 2);
                v += __shfl_down_sync(0xffffffffu, v, 1);
                if (lane == 0) s_cs[(qtr*8+c)*8 + wid] += v;
            }
        }
    }

    __syncthreads();
    if (tid < 32) {
        float s = 0.f;
        #pragma unroll
        for (int w = 0; w < 8; w++) s += s_cs[tid*8 + w];
        py[(b*128 + blkLocal)*32 + tid] = s;
    }
}

// alpha math, run by last gather block
__device__ void alpha_tail(const float* pz0, const float* py1, const float* py2,
                           const float* rw1, const float* rb1,
                           const float* rw2, const float* rb2,
                           float* alpha, float* sm, int tid)
{
    float* s_cat = sm;          // 384
    float* s_hid = sm + 384;    // 128
    float* s_lg  = sm + 512;    // 12
    if (tid < 128) {
        int b = tid >> 5, c = tid & 31;
        float s0 = 0.f;
        #pragma unroll 8
        for (int k = 0; k < 256; k++) s0 += pz0[((b<<8)+k)*32 + c];
        float s1 = 0.f;
        #pragma unroll 8
        for (int k = 0; k < 128; k++) s1 += py1[((b<<7)+k)*32 + c];
        float s2 = 0.f;
        #pragma unroll 8
        for (int k = 0; k < 128; k++) s2 += py2[((b<<7)+k)*32 + c];
        const float inv = 1.0f/65536.0f;
        s_cat[b*96 +      c] = s0*inv;
        s_cat[b*96 + 32 + c] = s1*inv;
        s_cat[b*96 + 64 + c] = s2*inv;
    }
    __syncthreads();
    if (tid < 128) {
        int b = tid >> 5, c = tid & 31;
        float a = rb1[c];
        const float* cat = s_cat + b*96;
        #pragma unroll 8
        for (int j = 0; j < 96; j++) a += cat[j]*rw1[j*32 + c];
        s_hid[b*32 + c] = a / (1.f + __expf(-a));
    }
    __syncthreads();
    if (tid < 12) {
        int bb = tid / 3, t2 = tid % 3;
        float a = rb2[t2];
        #pragma unroll
        for (int o = 0; o < 32; o++) a += s_hid[bb*32+o]*rw2[o*3+t2];
        s_lg[bb*3+t2] = a;
    }
    __syncthreads();
    if (tid < 4) {
        float l0 = s_lg[tid*3], l1 = s_lg[tid*3+1], l2 = s_lg[tid*3+2];
        float m = fmaxf(l0, fmaxf(l1, l2));
        float e0 = __expf(l0-m), e1 = __expf(l1-m), e2 = __expf(l2-m);
        float inv = 1.f/(e0+e1+e2);
        alpha[tid*3+0] = e0*inv; alpha[tid*3+1] = e1*inv; alpha[tid*3+2] = e2*inv;
    }
}

__global__ void __launch_bounds__(256, 5) gather_head_kernel(
    const float* __restrict__ z1, const float* __restrict__ z2,
    const float* __restrict__ o12a, const float* __restrict__ o12b,
    float* y1, float* y2, float* py1, float* py2,
    const float* pz0,
    const float* rw1, const float* rb1, const float* rw2, const float* rb2,
    float* alpha)
{
    __shared__ __align__(16) float smem[3456];
    __shared__ int s_last;
    int hb = blockIdx.x;
    int tid = threadIdx.x;
    if (hb < 512) {
        int local = hb & 127;
        gather_head_impl<128,128,40,10>(smem, z1, o12a, y1, py1,
                                        local & 3, local >> 2, hb >> 7, local);
    } else {
        int r = hb - 512;
        int local = r & 127;
        gather_head_impl<64,64,24,8>(smem, z2, o12b, y2, py2,
                                     local & 3, local >> 2, r >> 7, local);
    }
    __syncthreads();
    if (tid == 0) {
        __threadfence();
        int old = atomicAdd(&g_ctr, 1);
        s_last = (old == (int)gridDim.x - 1) ? 1 : 0;
    }
    __syncthreads();
    if (s_last) {
        if (tid == 0) { g_ctr = 0; __threadfence(); }
        alpha_tail(pz0, py1, py2, rw1, rb1, rw2, rb2, alpha, smem, tid);
    }
}

// ---------------- final: alpha-mix + 1x1 conv (f32x2) + residual; all CHW ----------------
__global__ void __launch_bounds__(256) final_kernel(
                             const float* __restrict__ x,
                             const float* __restrict__ z0,
                             const float* __restrict__ y1,
                             const float* __restrict__ y2,
                             const float* __restrict__ fw,
                             const float* __restrict__ alpha,
                             float* __restrict__ out)
{
    __shared__ __align__(16) float s_fwT[1024];   // [c][o]
    for (int i = threadIdx.x; i < 1024; i += 256) {
        int o = i >> 5, c = i & 31;
        s_fwT[c*32 + o] = fw[i];
    }
    __syncthreads();
    int b = blockIdx.y;
    int pix = blockIdx.x*256 + threadIdx.x;
    float a0 = alpha[b*3], a1 = alpha[b*3+1], a2 = alpha[b*3+2];
    size_t base = (size_t)b*32*65536 + pix;

    ull acc2[16];
    #pragma unroll
    for (int op = 0; op < 16; op++) acc2[op] = 0ull;

    #pragma unroll
    for (int c = 0; c < 32; c++) {
        size_t idx = base + (size_t)c*65536;
        float mval = a0*z0[idx] + a1*y1[idx] + a2*y2[idx];
        ull m2 = pack2(mval, mval);
        const float4* wrow = (const float4*)(s_fwT + c*32);
        #pragma unroll
        for (int oq = 0; oq < 8; oq++) {
            float4 w4 = wrow[oq];
            const ull* wp = (const ull*)&w4;
            acc2[oq*2+0] = ffma2(m2, wp[0], acc2[oq*2+0]);
            acc2[oq*2+1] = ffma2(m2, wp[1], acc2[oq*2+1]);
        }
    }
    #pragma unroll
    for (int op = 0; op < 16; op++) {
        float2 f = unpack2(acc2[op]);
        size_t i0 = base + (size_t)(2*op)*65536;
        size_t i1 = base + (size_t)(2*op+1)*65536;
        out[i0] = x[i0] + f.x;
        out[i1] = x[i1] + f.y;
    }
}

// ---------------- launch ----------------
extern "C" void kernel_launch(void* const* d_in, const int* in_sizes, int n_in,
                              void* d_out, int out_size)
{
    const float* x       = (const float*)d_in[0];
    const float* ds0_dw  = (const float*)d_in[1];
    const float* ds0_pw  = (const float*)d_in[2];
    const float* ds0_g   = (const float*)d_in[3];
    const float* ds0_b   = (const float*)d_in[4];
    const float* ds0_m   = (const float*)d_in[5];
    const float* ds0_v   = (const float*)d_in[6];
    const float* ds1_dw  = (const float*)d_in[7];
    const float* ds1_pw  = (const float*)d_in[8];
    const float* ds1_g   = (const float*)d_in[9];
    const float* ds1_b   = (const float*)d_in[10];
    const float* ds1_m   = (const float*)d_in[11];
    const float* ds1_v   = (const float*)d_in[12];
    const float* ds2_dw  = (const float*)d_in[13];
    const float* ds2_pw  = (const float*)d_in[14];
    const float* ds2_g   = (const float*)d_in[15];
    const float* ds2_b   = (const float*)d_in[16];
    const float* ds2_m   = (const float*)d_in[17];
    const float* ds2_v   = (const float*)d_in[18];
    const float* qproj_w = (const float*)d_in[19];
    const float* h1_w1   = (const float*)d_in[20];
    const float* h1_w2   = (const float*)d_in[21];
    const float* h1_b2   = (const float*)d_in[22];
    const float* h2_w1   = (const float*)d_in[23];
    const float* h2_w2   = (const float*)d_in[24];
    const float* h2_b2   = (const float*)d_in[25];
    const float* r_w1    = (const float*)d_in[26];
    const float* r_b1    = (const float*)d_in[27];
    const float* r_w2    = (const float*)d_in[28];
    const float* r_b2    = (const float*)d_in[29];
    const float* final_w = (const float*)d_in[30];
    float* out = (float*)d_out;

    float *z0, *q, *z1, *z2, *y1, *y2, *o12a, *o12b, *pz0, *py1, *py2, *alpha;
    cudaGetSymbolAddress((void**)&z0,    g_z0);
    cudaGetSymbolAddress((void**)&q,     g_q);
    cudaGetSymbolAddress((void**)&z1,    g_z1);
    cudaGetSymbolAddress((void**)&z2,    g_z2);
    cudaGetSymbolAddress((void**)&y1,    g_y1);
    cudaGetSymbolAddress((void**)&y2,    g_y2);
    cudaGetSymbolAddress((void**)&o12a,  g_o12a);
    cudaGetSymbolAddress((void**)&o12b,  g_o12b);
    cudaGetSymbolAddress((void**)&pz0,   g_pz0);
    cudaGetSymbolAddress((void**)&py1,   g_py1);
    cudaGetSymbolAddress((void**)&py2,   g_py2);
    cudaGetSymbolAddress((void**)&alpha, g_alpha);

    ds_fat_kernel<<<1344, 256>>>(x,
        ds0_dw, ds0_pw, ds0_g, ds0_b, ds0_m, ds0_v,
        ds1_dw, ds1_pw, ds1_g, ds1_b, ds1_m, ds1_v,
        ds2_dw, ds2_pw, ds2_g, ds2_b, ds2_m, ds2_v,
        qproj_w, z0, q, z1, z2, pz0);

    conv_head_kernel<<<1024, 256>>>(q,
        h1_w1, h1_w2, h1_b2, h2_w1, h2_w2, h2_b2, o12a, o12b);

    gather_head_kernel<<<1024, 256>>>(z1, z2, o12a, o12b,
        y1, y2, py1, py2, pz0, r_w1, r_b1, r_w2, r_b2, alpha);

    final_kernel<<<dim3(256,4), 256>>>(x, z0, y1, y2, final_w, alpha, out);
}

// round 16
// speedup vs baseline: 1.1207x; 1.1207x over previous
#include <cuda_runtime.h>
#include <math.h>
#include <stdint.h>

#define Bn 4
#define Cn 32
#define N0 (4*32*256*256)
#define N1 (4*32*128*128)
#define N2 (4*32*64*64)

typedef unsigned long long ull;

__device__ __forceinline__ ull pack2(float lo, float hi) {
    ull d;
    asm("mov.b64 %0, {%1, %2};" : "=l"(d) : "f"(lo), "f"(hi));
    return d;
}
__device__ __forceinline__ float2 unpack2(ull v) {
    float2 f;
    asm("mov.b64 {%0, %1}, %2;" : "=f"(f.x), "=f"(f.y) : "l"(v));
    return f;
}
__device__ __forceinline__ ull ffma2(ull a, ull b, ull c) {
    ull d;
    asm("fma.rn.f32x2 %0, %1, %2, %3;" : "=l"(d) : "l"(a), "l"(b), "l"(c));
    return d;
}

// ---------------- device scratch ----------------
__device__ float g_z0[N0];   // CHW
__device__ float g_q [N0];   // CHW
__device__ float g_z1[N1];   // HWC
__device__ float g_z2[N2];   // HWC
__device__ float g_y1[N0];   // CHW
__device__ float g_y2[N0];   // CHW
__device__ float g_pz0[4*256*32];
__device__ float g_py1[4*128*32];
__device__ float g_py2[4*128*32];
__device__ float g_alpha[12];
__device__ int   g_ctr = 0;

// ---------------- fused (inline-pool) + dwconv3(f32x2) + pw1x1(f32x2) + BN + SiLU (+ q-proj + partials) ----------------
template<int H, int W, int F, bool FUSEQ, bool HWC>
__device__ __forceinline__ void ds_impl(float* smem,
                          const float* __restrict__ x,
                          const float* __restrict__ dw,
                          const float* __restrict__ pw,
                          const float* __restrict__ gg,
                          const float* __restrict__ bb,
                          const float* __restrict__ mm,
                          const float* __restrict__ vv,
                          const float* __restrict__ qw,
                          float* __restrict__ z, float* __restrict__ q,
                          float* __restrict__ pz,
                          int bxi, int byi, int b, int blkLocal)
{
    float* s_tile = smem;            // 10368, pair-interleaved [cp][y][x][2]
    float* s_dw   = smem + 10368;    // 288
    int tid = threadIdx.x;
    int tx = tid & 15, ty = tid >> 4;
    int bx = bxi * 16, by = byi * 16;
    const float* xb = x + b*Cn*256*256;

    for (int i = tid; i < 32*324; i += 256) {
        int c = i / 324; int r = i % 324; int yy = r/18, xx = r%18;
        int gy = by + yy - 1, gx = bx + xx - 1;
        float val = 0.f;
        if (gy >= 0 && gy < H && gx >= 0 && gx < W) {
            if (F == 1) {
                val = xb[(c*256+gy)*256 + gx];
            } else if (F == 2) {
                const float2* p = (const float2*)(xb + (c*256 + 2*gy)*256 + 2*gx);
                float2 a = p[0], bq = p[128];
                val = 0.25f*(a.x + a.y + bq.x + bq.y);
            } else {
                const float4* p = (const float4*)(xb + (c*256 + 4*gy)*256 + 4*gx);
                float s = 0.f;
                #pragma unroll
                for (int fy = 0; fy < 4; fy++) {
                    float4 v4 = p[fy*64];
                    s += v4.x + v4.y + v4.z + v4.w;
                }
                val = s * 0.0625f;
            }
        }
        s_tile[((c >> 1)*324 + r)*2 + (c & 1)] = val;
    }
    for (int i = tid; i < 288; i += 256) {
        int c = i / 9, k = i % 9;
        s_dw[((c >> 1)*9 + k)*2 + (c & 1)] = dw[i];
    }
    __syncthreads();

    float t[32];
    #pragma unroll
    for (int cp = 0; cp < 16; cp++) {
        const float* tp = s_tile + (cp*324 + ty*18 + tx)*2;
        const float* wp = s_dw + cp*18;
        ull a2 = 0ull;
        #pragma unroll
        for (int ky = 0; ky < 3; ky++)
            #pragma unroll
            for (int kx = 0; kx < 3; kx++) {
                ull v2 = *(const ull*)(tp + (ky*18+kx)*2);
                ull w2 = *(const ull*)(wp + (ky*3+kx)*2);
                a2 = ffma2(v2, w2, a2);
            }
        float2 f = unpack2(a2);
        t[2*cp] = f.x; t[2*cp+1] = f.y;
    }
    __syncthreads();

    float* s_pwT = smem;             // [c][o], stride 36 (16B aligned)
    float* s_qwT = smem + 1152;
    float* s_sc  = smem + 2304;
    float* s_bi  = smem + 2336;
    for (int i = tid; i < 1024; i += 256) s_pwT[(i & 31)*36 + (i >> 5)] = pw[i];
    if (FUSEQ) for (int i = tid; i < 1024; i += 256) s_qwT[(i & 31)*36 + (i >> 5)] = qw[i];
    if (tid < 32) {
        float sc = gg[tid] * rsqrtf(vv[tid] + 1e-5f);
        s_sc[tid] = sc; s_bi[tid] = bb[tid] - mm[tid]*sc;
    }
    __syncthreads();

    int gy = by + ty, gx = bx + tx;
    float zl[32];
    {
        ull acc2[16];
        #pragma unroll
        for (int op = 0; op < 16; op++) acc2[op] = 0ull;
        #pragma unroll
        for (int c = 0; c < 32; c++) {
            ull m2 = pack2(t[c], t[c]);
            const float4* w4 = (const float4*)(s_pwT + c*36);
            #pragma unroll
            for (int oq = 0; oq < 8; oq++) {
                float4 w = w4[oq];
                const ull* wp = (const ull*)&w;
                acc2[oq*2+0] = ffma2(m2, wp[0], acc2[oq*2+0]);
                acc2[oq*2+1] = ffma2(m2, wp[1], acc2[oq*2+1]);
            }
        }
        #pragma unroll
        for (int op = 0; op < 16; op++) {
            float2 f = unpack2(acc2[op]);
            int o0 = 2*op, o1 = 2*op+1;
            float v0 = f.x*s_sc[o0] + s_bi[o0];
            float v1 = f.y*s_sc[o1] + s_bi[o1];
            zl[o0] = v0 / (1.f + __expf(-v0));
            zl[o1] = v1 / (1.f + __expf(-v1));
        }
    }
    if (HWC) {
        float4* zp4 = (float4*)(z + ((size_t)(b*H + gy)*W + gx)*32);
        #pragma unroll
        for (int j = 0; j < 8; j++)
            zp4[j] = make_float4(zl[4*j], zl[4*j+1], zl[4*j+2], zl[4*j+3]);
    } else {
        float* zp = z + ((size_t)b*Cn*H + gy)*W + gx;
        #pragma unroll
        for (int o = 0; o < 32; o++) zp[o*H*W] = zl[o];
    }
    if (FUSEQ) {
        float* qp = q + ((size_t)b*Cn*H + gy)*W + gx;
        #pragma unroll
        for (int half = 0; half < 2; half++) {
            ull acc2[8];
            #pragma unroll
            for (int op = 0; op < 8; op++) acc2[op] = 0ull;
            #pragma unroll
            for (int c = 0; c < 32; c++) {
                ull m2 = pack2(zl[c], zl[c]);
                const float4* w4 = (const float4*)(s_qwT + c*36) + half*4;
                #pragma unroll
                for (int oq = 0; oq < 4; oq++) {
                    float4 w = w4[oq];
                    const ull* wp = (const ull*)&w;
                    acc2[oq*2+0] = ffma2(m2, wp[0], acc2[oq*2+0]);
                    acc2[oq*2+1] = ffma2(m2, wp[1], acc2[oq*2+1]);
                }
            }
            #pragma unroll
            for (int op = 0; op < 8; op++) {
                float2 f = unpack2(acc2[op]);
                qp[(half*16 + 2*op)*H*W]   = f.x;
                qp[(half*16 + 2*op+1)*H*W] = f.y;
            }
        }
        __syncthreads();
        float* s_red = smem;
        int lane = tid & 31, wid = tid >> 5;
        #pragma unroll
        for (int c = 0; c < 32; c++) {
            float v = zl[c];
            v += __shfl_down_sync(0xffffffffu, v, 16);
            v += __shfl_down_sync(0xffffffffu, v, 8);
            v += __shfl_down_sync(0xffffffffu, v, 4);
            v += __shfl_down_sync(0xffffffffu, v, 2);
            v += __shfl_down_sync(0xffffffffu, v, 1);
            if (lane == 0) s_red[c*8 + wid] = v;
        }
        __syncthreads();
        if (tid < 32) {
            float s = 0.f;
            #pragma unroll
            for (int w = 0; w < 8; w++) s += s_red[tid*8 + w];
            pz[(b*256 + blkLocal)*32 + tid] = s;
        }
    }
}

__global__ void __launch_bounds__(256, 3) ds_fat_kernel(
    const float* __restrict__ x,
    const float* d0dw, const float* d0pw, const float* d0g, const float* d0b, const float* d0m, const float* d0v,
    const float* d1dw, const float* d1pw, const float* d1g, const float* d1b, const float* d1m, const float* d1v,
    const float* d2dw, const float* d2pw, const float* d2g, const float* d2b, const float* d2m, const float* d2v,
    const float* qw, float* z0, float* q, float* z1, float* z2, float* pz0)
{
    __shared__ __align__(16) float smem[10688];
    int bid = blockIdx.x;
    if (bid < 256) {
        ds_impl<128,128,2,false,true>(smem, x, d1dw, d1pw, d1g, d1b, d1m, d1v, nullptr, z1, nullptr, nullptr,
                                      bid & 7, (bid >> 3) & 7, bid >> 6, 0);
    } else if (bid < 320) {
        int r = bid - 256;
        ds_impl<64,64,4,false,true>(smem, x, d2dw, d2pw, d2g, d2b, d2m, d2v, nullptr, z2, nullptr, nullptr,
                                    r & 3, (r >> 2) & 3, r >> 4, 0);
    } else {
        int r = bid - 320;
        ds_impl<256,256,1,true,false>(smem, x, d0dw, d0pw, d0g, d0b, d0m, d0v, qw, z0, q, pz0,
                                      r & 15, (r >> 4) & 15, r >> 8, r & 255);
    }
}

// ---------------- offset head: low-reg variant for occ 4 ----------------
// smem region (10064 floats = 40.3KB):
//   conv phase:   tile [0..5440) | w1T [5440..6592)
//   gather phase: window [0..3200) | params [3200..9600) (256 thr x pitch 25)
//   fixed: w2 [9600..9792) | b2 [9792..9808) | cs [9808..10064)
template<int Hc, int Wc, int WX, int WY>
__device__ __forceinline__ void head_impl(float* smem,
                            const float* __restrict__ q,
                            const float* __restrict__ zc,   // HWC
                            const float* __restrict__ w1,
                            const float* __restrict__ w2,
                            const float* __restrict__ b2,
                            float* __restrict__ y,          // CHW
                            float* __restrict__ py,
                            int bxi, int byi, int b, int blkLocal)
{
    float* s_tile = smem;            // 5440
    float* s_w1   = smem + 5440;     // 1152
    float* s_par  = smem + 3200;     // 6400 (gather phase)
    float* s_w2   = smem + 9600;     // 192
    float* s_b2   = smem + 9792;     // 16
    float* s_cs   = smem + 9808;     // 256
    int tid = threadIdx.x;
    int tx = tid & 63;
    int tyq = tid >> 6;
    int bx = bxi*64, by = byi*8;
    int r0 = tyq*2;
    int lane = tid & 31, wid = tid >> 5;

    if (tid < 192) s_w2[tid] = w2[tid];
    if (tid >= 192 && tid < 204) s_b2[tid-192] = b2[tid-192];
    s_cs[tid] = 0.f;

    const float* qb = q + (size_t)b*32*65536;

    ull acc2[8][2];
    #pragma unroll
    for (int op = 0; op < 8; op++) { acc2[op][0] = 0ull; acc2[op][1] = 0ull; }

    for (int g = 0; g < 4; g++) {
        __syncthreads();
        for (int i = tid; i < 8*10*66; i += 256) {
            int c = i / 660; int r = i % 660; int yy = r/66, xx = r%66;
            int gy = by + yy - 1, gx = bx + xx - 1;
            float val = 0.f;
            if ((unsigned)gy < 256u && (unsigned)gx < 256u)
                val = qb[((g*8+c)*256 + gy)*256 + gx];
            s_tile[(c*10 + yy)*68 + xx] = val;
        }
        for (int i = tid; i < 1152; i += 256) {
            int cl = i / 144; int rem = i % 144; int kk = rem >> 4; int o = rem & 15;
            s_w1[i] = w1[(o*32 + g*8 + cl)*9 + kk];
        }
        __syncthreads();

        #pragma unroll
        for (int cl = 0; cl < 8; cl++) {
            const float* tp = s_tile + cl*680 + r0*68 + tx;
            const float* wbase = s_w1 + cl*144;
            #pragma unroll
            for (int ky = 0; ky < 3; ky++)
                #pragma unroll
                for (int kx = 0; kx < 3; kx++) {
                    int kk = ky*3 + kx;
                    float va = tp[ky*68 + kx];
                    float vb = tp[(ky+1)*68 + kx];
                    ull vd0 = pack2(va, va);
                    ull vd1 = pack2(vb, vb);
                    #pragma unroll
                    for (int oq = 0; oq < 4; oq++) {
                        float4 w4 = *(const float4*)(wbase + kk*16 + oq*4);
                        const ull* wp = (const ull*)&w4;
                        acc2[oq*2+0][0] = ffma2(wp[0], vd0, acc2[oq*2+0][0]);
                        acc2[oq*2+0][1] = ffma2(wp[0], vd1, acc2[oq*2+0][1]);
                        acc2[oq*2+1][0] = ffma2(wp[1], vd0, acc2[oq*2+1][0]);
                        acc2[oq*2+1][1] = ffma2(wp[1], vd1, acc2[oq*2+1][1]);
                    }
                }
        }
    }

    // SiLU + conv1x1 + softmax/tanh -> params to smem
    __syncthreads();   // tile region done; params region becomes writable
    int gx = bx + tx;
    float xc = (gx + 0.5f)*((float)Wc/256.f) - 0.5f;
    {
        float h[2][16];
        #pragma unroll
        for (int op = 0; op < 8; op++)
            #pragma unroll
            for (int r = 0; r < 2; r++) {
                float2 f = unpack2(acc2[op][r]);
                h[r][2*op]   = f.x / (1.f + __expf(-f.x));
                h[r][2*op+1] = f.y / (1.f + __expf(-f.y));
            }
        float* pp = s_par + tid*25;
        #pragma unroll
        for (int r = 0; r < 2; r++) {
            float op[12];
            #pragma unroll
            for (int j = 0; j < 12; j++) {
                float a = s_b2[j];
                #pragma unroll
                for (int i = 0; i < 16; i++) a += s_w2[j*16+i]*h[r][i];
                op[j] = a;
            }
            int gy = by + r0 + r;
            float ycf = (gy + 0.5f)*((float)Hc/256.f) - 0.5f;
            float mlog = fmaxf(fmaxf(op[8],op[9]), fmaxf(op[10],op[11]));
            float e[4]; float es = 0.f;
            #pragma unroll
            for (int k = 0; k < 4; k++) { e[k] = __expf(op[8+k]-mlog); es += e[k]; }
            float inv = 1.f/es;
            #pragma unroll
            for (int k = 0; k < 4; k++) {
                pp[r*12 + k] = e[k]*inv;
                float ix = xc + 2.0f*tanhf(op[2*k]);
                float iy = ycf + 2.0f*tanhf(op[2*k+1]);
                pp[r*12 + 4 + k] = fminf(fmaxf(ix, 0.f), (float)(Wc-1));
                pp[r*12 + 8 + k] = fminf(fmaxf(iy, 0.f), (float)(Hc-1));
            }
        }
    }

    int cx0 = (bx*Wc >> 8) - 3;
    int cy0 = (by*Hc >> 8) - 3;
    const float4* zb4 = (const float4*)(zc + (size_t)b*Hc*Wc*32);
    const float* pp = s_par + tid*25;

    for (int qtr = 0; qtr < 4; qtr++) {
        __syncthreads();
        for (int i = tid; i < WX*WY*2; i += 256) {
            int cell = i >> 1, j = i & 1;
            int wy = cell / WX, wx = cell - wy*WX;
            int gyc = min(max(cy0 + wy, 0), Hc-1);
            int gxc = min(max(cx0 + wx, 0), Wc-1);
            ((float4*)smem)[i] = __ldg(zb4 + (size_t)(gyc*Wc + gxc)*8 + qtr*2 + j);
        }
        __syncthreads();
        const float4* w4 = (const float4*)smem;

        #pragma unroll
        for (int r = 0; r < 2; r++) {
            int gy = by + r0 + r;
            ull yac2[4];
            #pragma unroll
            for (int v = 0; v < 4; v++) yac2[v] = 0ull;
            #pragma unroll
            for (int k = 0; k < 4; k++) {
                float wk = pp[r*12 + k];
                float ix = pp[r*12 + 4 + k];
                float iy = pp[r*12 + 8 + k];
                float x0 = floorf(ix), y0 = floorf(iy);
                float wxr = ix-x0, wyr = iy-y0;
                int x0i = (int)x0, y0i = (int)y0;
                int x1i = min(x0i+1, Wc-1), y1i = min(y0i+1, Hc-1);
                float w00 = wk*(1.f-wxr)*(1.f-wyr), w01 = wk*wxr*(1.f-wyr);
                float w10 = wk*(1.f-wxr)*wyr,       w11 = wk*wxr*wyr;
                ull W00 = pack2(w00,w00), W01 = pack2(w01,w01);
                ull W10 = pack2(w10,w10), W11 = pack2(w11,w11);
                int lx0 = x0i - cx0, lx1 = x1i - cx0;
                int ly0 = y0i - cy0, ly1 = y1i - cy0;
                int i00 = (ly0*WX + lx0)*2, i01 = (ly0*WX + lx1)*2;
                int i10 = (ly1*WX + lx0)*2, i11 = (ly1*WX + lx1)*2;
                #pragma unroll
                for (int v = 0; v < 2; v++) {
                    float4 a00 = w4[i00 + v];
                    float4 a01 = w4[i01 + v];
                    float4 a10 = w4[i10 + v];
                    float4 a11 = w4[i11 + v];
                    const ull* p00 = (const ull*)&a00;
                    const ull* p01 = (const ull*)&a01;
                    const ull* p10 = (const ull*)&a10;
                    const ull* p11 = (const ull*)&a11;
                    #pragma unroll
                    for (int hh = 0; hh < 2; hh++) {
                        ull acc = yac2[v*2+hh];
                        acc = ffma2(W00, p00[hh], acc);
                        acc = ffma2(W01, p01[hh], acc);
                        acc = ffma2(W10, p10[hh], acc);
                        acc = ffma2(W11, p11[hh], acc);
                        yac2[v*2+hh] = acc;
                    }
                }
            }
            float* yp = y + (((size_t)b*32 + qtr*8)*256 + gy)*256 + gx;
            const float* yf = (const float*)yac2;
            #pragma unroll
            for (int c = 0; c < 8; c++) yp[c*65536] = yf[c];
            #pragma unroll
            for (int c = 0; c < 8; c++) {
                float v = yf[c];
                v += __shfl_down_sync(0xffffffffu, v, 16);
                v += __shfl_down_sync(0xffffffffu, v, 8);
                v += __shfl_down_sync(0xffffffffu, v, 4);
                v += __shfl_down_sync(0xffffffffu, v, 2);
                v += __shfl_down_sync(0xffffffffu, v, 1);
                if (lane == 0) s_cs[(qtr*8+c)*8 + wid] += v;
            }
        }
    }

    __syncthreads();
    if (tid < 32) {
        float s = 0.f;
        #pragma unroll
        for (int w = 0; w < 8; w++) s += s_cs[tid*8 + w];
        py[(b*128 + blkLocal)*32 + tid] = s;
    }
}

// alpha math, run by last head block
__device__ void alpha_tail(const float* pz0, const float* py1, const float* py2,
                           const float* rw1, const float* rb1,
                           const float* rw2, const float* rb2,
                           float* alpha, float* sm, int tid)
{
    float* s_cat = sm;          // 384
    float* s_hid = sm + 384;    // 128
    float* s_lg  = sm + 512;    // 12
    if (tid < 128) {
        int b = tid >> 5, c = tid & 31;
        float s0 = 0.f;
        #pragma unroll 8
        for (int k = 0; k < 256; k++) s0 += pz0[((b<<8)+k)*32 + c];
        float s1 = 0.f;
        #pragma unroll 8
        for (int k = 0; k < 128; k++) s1 += py1[((b<<7)+k)*32 + c];
        float s2 = 0.f;
        #pragma unroll 8
        for (int k = 0; k < 128; k++) s2 += py2[((b<<7)+k)*32 + c];
        const float inv = 1.0f/65536.0f;
        s_cat[b*96 +      c] = s0*inv;
        s_cat[b*96 + 32 + c] = s1*inv;
        s_cat[b*96 + 64 + c] = s2*inv;
    }
    __syncthreads();
    if (tid < 128) {
        int b = tid >> 5, c = tid & 31;
        float a = rb1[c];
        const float* cat = s_cat + b*96;
        #pragma unroll 8
        for (int j = 0; j < 96; j++) a += cat[j]*rw1[j*32 + c];
        s_hid[b*32 + c] = a / (1.f + __expf(-a));
    }
    __syncthreads();
    if (tid < 12) {
        int bb = tid / 3, t2 = tid % 3;
        float a = rb2[t2];
        #pragma unroll
        for (int o = 0; o < 32; o++) a += s_hid[bb*32+o]*rw2[o*3+t2];
        s_lg[bb*3+t2] = a;
    }
    __syncthreads();
    if (tid < 4) {
        float l0 = s_lg[tid*3], l1 = s_lg[tid*3+1], l2 = s_lg[tid*3+2];
        float m = fmaxf(l0, fmaxf(l1, l2));
        float e0 = __expf(l0-m), e1 = __expf(l1-m), e2 = __expf(l2-m);
        float inv = 1.f/(e0+e1+e2);
        alpha[tid*3+0] = e0*inv; alpha[tid*3+1] = e1*inv; alpha[tid*3+2] = e2*inv;
    }
}

__global__ void __launch_bounds__(256, 4) head_fat_kernel(
    const float* __restrict__ q,
    const float* __restrict__ z1, const float* __restrict__ z2,
    const float* h1w1, const float* h1w2, const float* h1b2,
    const float* h2w1, const float* h2w2, const float* h2b2,
    float* y1, float* y2, float* py1, float* py2,
    const float* pz0,
    const float* rw1, const float* rb1, const float* rw2, const float* rb2,
    float* alpha)
{
    __shared__ __align__(16) float smem[10064];
    __shared__ int s_last;
    int hb = blockIdx.x;
    int tid = threadIdx.x;
    if (hb < 512) {
        int local = hb & 127;
        head_impl<128,128,40,10>(smem, q, z1, h1w1, h1w2, h1b2, y1, py1,
                                 local & 3, local >> 2, hb >> 7, local);
    } else {
        int r = hb - 512;
        int local = r & 127;
        head_impl<64,64,24,8>(smem, q, z2, h2w1, h2w2, h2b2, y2, py2,
                              local & 3, local >> 2, r >> 7, local);
    }
    __syncthreads();
    if (tid == 0) {
        __threadfence();
        int old = atomicAdd(&g_ctr, 1);
        s_last = (old == (int)gridDim.x - 1) ? 1 : 0;
    }
    __syncthreads();
    if (s_last) {
        if (tid == 0) { g_ctr = 0; __threadfence(); }
        alpha_tail(pz0, py1, py2, rw1, rb1, rw2, rb2, alpha, smem, tid);
    }
}

// ---------------- final: alpha-mix + 1x1 conv (f32x2) + residual; all CHW ----------------
__global__ void __launch_bounds__(256, 4) final_kernel(
                             const float* __restrict__ x,
                             const float* __restrict__ z0,
                             const float* __restrict__ y1,
                             const float* __restrict__ y2,
                             const float* __restrict__ fw,
                             const float* __restrict__ alpha,
                             float* __restrict__ out)
{
    __shared__ __align__(16) float s_fwT[1024];   // [c][o]
    for (int i = threadIdx.x; i < 1024; i += 256) {
        int o = i >> 5, c = i & 31;
        s_fwT[c*32 + o] = fw[i];
    }
    __syncthreads();
    int b = blockIdx.y;
    int pix = blockIdx.x*256 + threadIdx.x;
    float a0 = alpha[b*3], a1 = alpha[b*3+1], a2 = alpha[b*3+2];
    size_t base = (size_t)b*32*65536 + pix;

    ull acc2[16];
    #pragma unroll
    for (int op = 0; op < 16; op++) acc2[op] = 0ull;

    #pragma unroll
    for (int c = 0; c < 32; c++) {
        size_t idx = base + (size_t)c*65536;
        float mval = a0*z0[idx] + a1*y1[idx] + a2*y2[idx];
        ull m2 = pack2(mval, mval);
        const float4* wrow = (const float4*)(s_fwT + c*32);
        #pragma unroll
        for (int oq = 0; oq < 8; oq++) {
            float4 w4 = wrow[oq];
            const ull* wp = (const ull*)&w4;
            acc2[oq*2+0] = ffma2(m2, wp[0], acc2[oq*2+0]);
            acc2[oq*2+1] = ffma2(m2, wp[1], acc2[oq*2+1]);
        }
    }
    #pragma unroll
    for (int op = 0; op < 16; op++) {
        float2 f = unpack2(acc2[op]);
        size_t i0 = base + (size_t)(2*op)*65536;
        size_t i1 = base + (size_t)(2*op+1)*65536;
        out[i0] = x[i0] + f.x;
        out[i1] = x[i1] + f.y;
    }
}

// ---------------- launch ----------------
extern "C" void kernel_launch(void* const* d_in, const int* in_sizes, int n_in,
                              void* d_out, int out_size)
{
    const float* x       = (const float*)d_in[0];
    const float* ds0_dw  = (const float*)d_in[1];
    const float* ds0_pw  = (const float*)d_in[2];
    const float* ds0_g   = (const float*)d_in[3];
    const float* ds0_b   = (const float*)d_in[4];
    const float* ds0_m   = (const float*)d_in[5];
    const float* ds0_v   = (const float*)d_in[6];
    const float* ds1_dw  = (const float*)d_in[7];
    const float* ds1_pw  = (const float*)d_in[8];
    const float* ds1_g   = (const float*)d_in[9];
    const float* ds1_b   = (const float*)d_in[10];
    const float* ds1_m   = (const float*)d_in[11];
    const float* ds1_v   = (const float*)d_in[12];
    const float* ds2_dw  = (const float*)d_in[13];
    const float* ds2_pw  = (const float*)d_in[14];
    const float* ds2_g   = (const float*)d_in[15];
    const float* ds2_b   = (const float*)d_in[16];
    const float* ds2_m   = (const float*)d_in[17];
    const float* ds2_v   = (const float*)d_in[18];
    const float* qproj_w = (const float*)d_in[19];
    const float* h1_w1   = (const float*)d_in[20];
    const float* h1_w2   = (const float*)d_in[21];
    const float* h1_b2   = (const float*)d_in[22];
    const float* h2_w1   = (const float*)d_in[23];
    const float* h2_w2   = (const float*)d_in[24];
    const float* h2_b2   = (const float*)d_in[25];
    const float* r_w1    = (const float*)d_in[26];
    const float* r_b1    = (const float*)d_in[27];
    const float* r_w2    = (const float*)d_in[28];
    const float* r_b2    = (const float*)d_in[29];
    const float* final_w = (const float*)d_in[30];
    float* out = (float*)d_out;

    float *z0, *q, *z1, *z2, *y1, *y2, *pz0, *py1, *py2, *alpha;
    cudaGetSymbolAddress((void**)&z0,    g_z0);
    cudaGetSymbolAddress((void**)&q,     g_q);
    cudaGetSymbolAddress((void**)&z1,    g_z1);
    cudaGetSymbolAddress((void**)&z2,    g_z2);
    cudaGetSymbolAddress((void**)&y1,    g_y1);
    cudaGetSymbolAddress((void**)&y2,    g_y2);
    cudaGetSymbolAddress((void**)&pz0,   g_pz0);
    cudaGetSymbolAddress((void**)&py1,   g_py1);
    cudaGetSymbolAddress((void**)&py2,   g_py2);
    cudaGetSymbolAddress((void**)&alpha, g_alpha);

    ds_fat_kernel<<<1344, 256>>>(x,
        ds0_dw, ds0_pw, ds0_g, ds0_b, ds0_m, ds0_v,
        ds1_dw, ds1_pw, ds1_g, ds1_b, ds1_m, ds1_v,
        ds2_dw, ds2_pw, ds2_g, ds2_b, ds2_m, ds2_v,
        qproj_w, z0, q, z1, z2, pz0);

    head_fat_kernel<<<1024, 256>>>(q, z1, z2,
        h1_w1, h1_w2, h1_b2, h2_w1, h2_w2, h2_b2, y1, y2, py1, py2,
        pz0, r_w1, r_b1, r_w2, r_b2, alpha);

    final_kernel<<<dim3(256,4), 256>>>(x, z0, y1, y2, final_w, alpha, out);
}

// round 17
// speedup vs baseline: 1.1643x; 1.0389x over previous
#include <cuda_runtime.h>
#include <math.h>
#include <stdint.h>

#define Bn 4
#define Cn 32
#define N0 (4*32*256*256)
#define N1 (4*32*128*128)
#define N2 (4*32*64*64)

typedef unsigned long long ull;

__device__ __forceinline__ ull pack2(float lo, float hi) {
    ull d;
    asm("mov.b64 %0, {%1, %2};" : "=l"(d) : "f"(lo), "f"(hi));
    return d;
}
__device__ __forceinline__ float2 unpack2(ull v) {
    float2 f;
    asm("mov.b64 {%0, %1}, %2;" : "=f"(f.x), "=f"(f.y) : "l"(v));
    return f;
}
__device__ __forceinline__ ull ffma2(ull a, ull b, ull c) {
    ull d;
    asm("fma.rn.f32x2 %0, %1, %2, %3;" : "=l"(d) : "l"(a), "l"(b), "l"(c));
    return d;
}

// ---------------- device scratch ----------------
__device__ float g_z0[N0];   // CHW
__device__ float g_q [N0];   // CHW
__device__ float g_z1[N1];   // HWC
__device__ float g_z2[N2];   // HWC
__device__ float g_y1[N0];   // CHW
__device__ float g_y2[N0];   // CHW
__device__ float g_pz0[4*256*32];
__device__ float g_py1[4*128*32];
__device__ float g_py2[4*128*32];
__device__ float g_alpha[12];
__device__ int   g_ctr = 0;

// ---------------- fused (inline-pool) + dwconv3(f32x2) + pw1x1(f32x2) + BN + SiLU (+ q-proj + partials) ----------------
template<int H, int W, int F, bool FUSEQ, bool HWC>
__device__ __forceinline__ void ds_impl(float* smem,
                          const float* __restrict__ x,
                          const float* __restrict__ dw,
                          const float* __restrict__ pw,
                          const float* __restrict__ gg,
                          const float* __restrict__ bb,
                          const float* __restrict__ mm,
                          const float* __restrict__ vv,
                          const float* __restrict__ qw,
                          float* __restrict__ z, float* __restrict__ q,
                          float* __restrict__ pz,
                          int bxi, int byi, int b, int blkLocal)
{
    float* s_tile = smem;            // 10368, pair-interleaved [cp][y][x][2]
    float* s_dw   = smem + 10368;    // 288
    int tid = threadIdx.x;
    int tx = tid & 15, ty = tid >> 4;
    int bx = bxi * 16, by = byi * 16;
    const float* xb = x + b*Cn*256*256;

    // incremental c/r tracking (stride 256 < 324: at most one wrap per step)
    {
        int c = 0, r = tid;
        for (int i = tid; i < 32*324; i += 256) {
            int yy = r/18, xx = r - yy*18;
            int gy = by + yy - 1, gx = bx + xx - 1;
            float val = 0.f;
            if (gy >= 0 && gy < H && gx >= 0 && gx < W) {
                if (F == 1) {
                    val = xb[(c*256+gy)*256 + gx];
                } else if (F == 2) {
                    const float2* p = (const float2*)(xb + (c*256 + 2*gy)*256 + 2*gx);
                    float2 a = p[0], bq = p[128];
                    val = 0.25f*(a.x + a.y + bq.x + bq.y);
                } else {
                    const float4* p = (const float4*)(xb + (c*256 + 4*gy)*256 + 4*gx);
                    float s = 0.f;
                    #pragma unroll
                    for (int fy = 0; fy < 4; fy++) {
                        float4 v4 = p[fy*64];
                        s += v4.x + v4.y + v4.z + v4.w;
                    }
                    val = s * 0.0625f;
                }
            }
            s_tile[((c >> 1)*324 + r)*2 + (c & 1)] = val;
            r += 256;
            if (r >= 324) { r -= 324; c += 1; }
        }
    }
    for (int i = tid; i < 288; i += 256) {
        int c = i / 9, k = i - c*9;
        s_dw[((c >> 1)*9 + k)*2 + (c & 1)] = dw[i];
    }
    __syncthreads();

    float t[32];
    #pragma unroll
    for (int cp = 0; cp < 16; cp++) {
        const float* tp = s_tile + (cp*324 + ty*18 + tx)*2;
        const float* wp = s_dw + cp*18;
        ull a2 = 0ull;
        #pragma unroll
        for (int ky = 0; ky < 3; ky++)
            #pragma unroll
            for (int kx = 0; kx < 3; kx++) {
                ull v2 = *(const ull*)(tp + (ky*18+kx)*2);
                ull w2 = *(const ull*)(wp + (ky*3+kx)*2);
                a2 = ffma2(v2, w2, a2);
            }
        float2 f = unpack2(a2);
        t[2*cp] = f.x; t[2*cp+1] = f.y;
    }
    __syncthreads();

    // transposed weights, row stride 36 floats (16B aligned rows, LDS.128)
    float* s_pwT = smem;             // 1152
    float* s_qwT = smem + 1152;      // 1152
    float* s_sc  = smem + 2304;
    float* s_bi  = smem + 2336;
    for (int i = tid; i < 1024; i += 256) s_pwT[(i & 31)*36 + (i >> 5)] = pw[i];
    if (FUSEQ) for (int i = tid; i < 1024; i += 256) s_qwT[(i & 31)*36 + (i >> 5)] = qw[i];
    if (tid < 32) {
        float sc = gg[tid] * rsqrtf(vv[tid] + 1e-5f);
        s_sc[tid] = sc; s_bi[tid] = bb[tid] - mm[tid]*sc;
    }
    __syncthreads();

    int gy = by + ty, gx = bx + tx;
    float zl[32];
    {
        ull acc2[16];
        #pragma unroll
        for (int op = 0; op < 16; op++) acc2[op] = 0ull;
        #pragma unroll
        for (int c = 0; c < 32; c++) {
            ull m2 = pack2(t[c], t[c]);
            const float4* w4 = (const float4*)(s_pwT + c*36);
            #pragma unroll
            for (int oq = 0; oq < 8; oq++) {
                float4 w = w4[oq];
                const ull* wp = (const ull*)&w;
                acc2[oq*2+0] = ffma2(m2, wp[0], acc2[oq*2+0]);
                acc2[oq*2+1] = ffma2(m2, wp[1], acc2[oq*2+1]);
            }
        }
        #pragma unroll
        for (int op = 0; op < 16; op++) {
            float2 f = unpack2(acc2[op]);
            int o0 = 2*op, o1 = 2*op+1;
            float v0 = f.x*s_sc[o0] + s_bi[o0];
            float v1 = f.y*s_sc[o1] + s_bi[o1];
            zl[o0] = v0 / (1.f + __expf(-v0));
            zl[o1] = v1 / (1.f + __expf(-v1));
        }
    }
    if (HWC) {
        float4* zp4 = (float4*)(z + ((size_t)(b*H + gy)*W + gx)*32);
        #pragma unroll
        for (int j = 0; j < 8; j++)
            zp4[j] = make_float4(zl[4*j], zl[4*j+1], zl[4*j+2], zl[4*j+3]);
    } else {
        float* zp = z + ((size_t)b*Cn*H + gy)*W + gx;
        #pragma unroll
        for (int o = 0; o < 32; o++) zp[o*H*W] = zl[o];
    }
    if (FUSEQ) {
        float* qp = q + ((size_t)b*Cn*H + gy)*W + gx;
        // two output halves: acc footprint 8 ull instead of 16
        #pragma unroll
        for (int half = 0; half < 2; half++) {
            ull acc2[8];
            #pragma unroll
            for (int op = 0; op < 8; op++) acc2[op] = 0ull;
            #pragma unroll
            for (int c = 0; c < 32; c++) {
                ull m2 = pack2(zl[c], zl[c]);
                const float4* w4 = (const float4*)(s_qwT + c*36) + half*4;
                #pragma unroll
                for (int oq = 0; oq < 4; oq++) {
                    float4 w = w4[oq];
                    const ull* wp = (const ull*)&w;
                    acc2[oq*2+0] = ffma2(m2, wp[0], acc2[oq*2+0]);
                    acc2[oq*2+1] = ffma2(m2, wp[1], acc2[oq*2+1]);
                }
            }
            #pragma unroll
            for (int op = 0; op < 8; op++) {
                float2 f = unpack2(acc2[op]);
                qp[(half*16 + 2*op)*H*W]   = f.x;
                qp[(half*16 + 2*op+1)*H*W] = f.y;
            }
        }
        __syncthreads();
        float* s_red = smem;
        int lane = tid & 31, wid = tid >> 5;
        #pragma unroll
        for (int c = 0; c < 32; c++) {
            float v = zl[c];
            v += __shfl_down_sync(0xffffffffu, v, 16);
            v += __shfl_down_sync(0xffffffffu, v, 8);
            v += __shfl_down_sync(0xffffffffu, v, 4);
            v += __shfl_down_sync(0xffffffffu, v, 2);
            v += __shfl_down_sync(0xffffffffu, v, 1);
            if (lane == 0) s_red[c*8 + wid] = v;
        }
        __syncthreads();
        if (tid < 32) {
            float s = 0.f;
            #pragma unroll
            for (int w = 0; w < 8; w++) s += s_red[tid*8 + w];
            pz[(b*256 + blkLocal)*32 + tid] = s;
        }
    }
}

__global__ void __launch_bounds__(256, 3) ds_fat_kernel(
    const float* __restrict__ x,
    const float* d0dw, const float* d0pw, const float* d0g, const float* d0b, const float* d0m, const float* d0v,
    const float* d1dw, const float* d1pw, const float* d1g, const float* d1b, const float* d1m, const float* d1v,
    const float* d2dw, const float* d2pw, const float* d2g, const float* d2b, const float* d2m, const float* d2v,
    const float* qw, float* z0, float* q, float* z1, float* z2, float* pz0)
{
    __shared__ __align__(16) float smem[10688];
    int bid = blockIdx.x;
    if (bid < 256) {
        ds_impl<128,128,2,false,true>(smem, x, d1dw, d1pw, d1g, d1b, d1m, d1v, nullptr, z1, nullptr, nullptr,
                                      bid & 7, (bid >> 3) & 7, bid >> 6, 0);
    } else if (bid < 320) {
        int r = bid - 256;
        ds_impl<64,64,4,false,true>(smem, x, d2dw, d2pw, d2g, d2b, d2m, d2v, nullptr, z2, nullptr, nullptr,
                                    r & 3, (r >> 2) & 3, r >> 4, 0);
    } else {
        int r = bid - 320;
        ds_impl<256,256,1,true,false>(smem, x, d0dw, d0pw, d0g, d0b, d0m, d0v, qw, z0, q, pz0,
                                      r & 15, (r >> 4) & 15, r >> 8, r & 255);
    }
}

// ---------------- offset head (R13) + f32x2 gather ----------------
template<int Hc, int Wc, int WX, int WY>
__device__ __forceinline__ void head_impl(float* smem,
                            const float* __restrict__ q,
                            const float* __restrict__ zc,   // HWC
                            const float* __restrict__ w1,
                            const float* __restrict__ w2,
                            const float* __restrict__ b2,
                            float* __restrict__ y,          // CHW
                            float* __restrict__ py,
                            int bxi, int byi, int b, int blkLocal)
{
    float* s_tile = smem;            // 5440 region
    float* s_w1   = smem + 5440;     // 1152
    float* s_w2   = s_w1 + 1152;     // 192
    float* s_b2   = s_w2 + 192;      // 16
    float* s_cs   = s_b2 + 16;       // 256
    int tid = threadIdx.x;
    int tx = tid & 63;
    int tyq = tid >> 6;
    int bx = bxi*64, by = byi*8;
    int r0 = tyq*2;
    int lane = tid & 31, wid = tid >> 5;

    if (tid < 192) s_w2[tid] = w2[tid];
    if (tid >= 192 && tid < 204) s_b2[tid-192] = b2[tid-192];
    s_cs[tid] = 0.f;

    const float* qb = q + (size_t)b*32*65536;

    ull acc2[8][2];
    #pragma unroll
    for (int op = 0; op < 8; op++) { acc2[op][0] = 0ull; acc2[op][1] = 0ull; }

    for (int g = 0; g < 4; g++) {
        __syncthreads();
        {
            int c = 0, r = tid;   // stride 256 < 660: one wrap max
            for (int i = tid; i < 8*10*66; i += 256) {
                int yy = r/66, xx = r - yy*66;
                int gy = by + yy - 1, gx = bx + xx - 1;
                float val = 0.f;
                if ((unsigned)gy < 256u && (unsigned)gx < 256u)
                    val = qb[((g*8+c)*256 + gy)*256 + gx];
                s_tile[(c*10 + yy)*68 + xx] = val;
                r += 256;
                if (r >= 660) { r -= 660; c += 1; }
            }
        }
        for (int i = tid; i < 1152; i += 256) {
            int cl = i / 144; int rem = i - cl*144; int kk = rem >> 4; int o = rem & 15;
            s_w1[i] = w1[(o*32 + g*8 + cl)*9 + kk];
        }
        __syncthreads();

        #pragma unroll
        for (int cl = 0; cl < 8; cl++) {
            float v[4][3];
            const float* tp = s_tile + cl*680 + r0*68 + tx;
            #pragma unroll
            for (int rr = 0; rr < 4; rr++)
                #pragma unroll
                for (int cc = 0; cc < 3; cc++) v[rr][cc] = tp[rr*68 + cc];
            ull vd[4][3];
            #pragma unroll
            for (int rr = 0; rr < 4; rr++)
                #pragma unroll
                for (int cc = 0; cc < 3; cc++) vd[rr][cc] = pack2(v[rr][cc], v[rr][cc]);
            const float* wbase = s_w1 + cl*144;
            #pragma unroll
            for (int ky = 0; ky < 3; ky++)
                #pragma unroll
                for (int kx = 0; kx < 3; kx++) {
                    int kk = ky*3 + kx;
                    #pragma unroll
                    for (int oq = 0; oq < 4; oq++) {
                        float4 w4 = *(const float4*)(wbase + kk*16 + oq*4);
                        const ull* wp = (const ull*)&w4;
                        #pragma unroll
                        for (int r = 0; r < 2; r++) {
                            acc2[oq*2+0][r] = ffma2(wp[0], vd[r+ky][kx], acc2[oq*2+0][r]);
                            acc2[oq*2+1][r] = ffma2(wp[1], vd[r+ky][kx], acc2[oq*2+1][r]);
                        }
                    }
                }
        }
    }

    float h[2][16];
    #pragma unroll
    for (int op = 0; op < 8; op++)
        #pragma unroll
        for (int r = 0; r < 2; r++) {
            float2 f = unpack2(acc2[op][r]);
            h[r][2*op]   = f.x / (1.f + __expf(-f.x));
            h[r][2*op+1] = f.y / (1.f + __expf(-f.y));
        }

    float o12[2][12];
    #pragma unroll
    for (int r = 0; r < 2; r++)
        #pragma unroll
        for (int j = 0; j < 12; j++) {
            float a = s_b2[j];
            #pragma unroll
            for (int i = 0; i < 16; i++) a += s_w2[j*16+i]*h[r][i];
            o12[r][j] = a;
        }

    int cx0 = (bx*Wc >> 8) - 3;
    int cy0 = (by*Hc >> 8) - 3;
    int gx = bx + tx;
    float xc = (gx + 0.5f)*((float)Wc/256.f) - 0.5f;

    float swk[2][4], six[2][4], siy[2][4];
    #pragma unroll
    for (int r = 0; r < 2; r++) {
        int gy = by + r0 + r;
        float ycf = (gy + 0.5f)*((float)Hc/256.f) - 0.5f;
        float* op = o12[r];
        float mlog = fmaxf(fmaxf(op[8],op[9]), fmaxf(op[10],op[11]));
        float e[4]; float es = 0.f;
        #pragma unroll
        for (int k = 0; k < 4; k++) { e[k] = __expf(op[8+k]-mlog); es += e[k]; }
        float inv = 1.f/es;
        #pragma unroll
        for (int k = 0; k < 4; k++) {
            swk[r][k] = e[k]*inv;
            float ix = xc + 2.0f*tanhf(op[2*k]);
            float iy = ycf + 2.0f*tanhf(op[2*k+1]);
            six[r][k] = fminf(fmaxf(ix, 0.f), (float)(Wc-1));
            siy[r][k] = fminf(fmaxf(iy, 0.f), (float)(Hc-1));
        }
    }

    const float4* zb4 = (const float4*)(zc + (size_t)b*Hc*Wc*32);

    for (int qtr = 0; qtr < 4; qtr++) {
        __syncthreads();
        for (int i = tid; i < WX*WY*2; i += 256) {
            int cell = i >> 1, j = i & 1;
            int wy = cell / WX, wx = cell - wy*WX;
            int gyc = min(max(cy0 + wy, 0), Hc-1);
            int gxc = min(max(cx0 + wx, 0), Wc-1);
            ((float4*)s_tile)[i] = zb4[(size_t)(gyc*Wc + gxc)*8 + qtr*2 + j];
        }
        __syncthreads();
        const float4* w4 = (const float4*)s_tile;

        #pragma unroll
        for (int r = 0; r < 2; r++) {
            int gy = by + r0 + r;
            ull yac2[4];
            #pragma unroll
            for (int v = 0; v < 4; v++) yac2[v] = 0ull;
            #pragma unroll
            for (int k = 0; k < 4; k++) {
                float wk = swk[r][k];
                float ix = six[r][k], iy = siy[r][k];
                float x0 = floorf(ix), y0 = floorf(iy);
                float wxr = ix-x0, wyr = iy-y0;
                int x0i = (int)x0, y0i = (int)y0;
                int x1i = min(x0i+1, Wc-1), y1i = min(y0i+1, Hc-1);
                float w00 = wk*(1.f-wxr)*(1.f-wyr), w01 = wk*wxr*(1.f-wyr);
                float w10 = wk*(1.f-wxr)*wyr,       w11 = wk*wxr*wyr;
                ull W00 = pack2(w00,w00), W01 = pack2(w01,w01);
                ull W10 = pack2(w10,w10), W11 = pack2(w11,w11);
                int lx0 = x0i - cx0, lx1 = x1i - cx0;
                int ly0 = y0i - cy0, ly1 = y1i - cy0;
                int i00 = (ly0*WX + lx0)*2, i01 = (ly0*WX + lx1)*2;
                int i10 = (ly1*WX + lx0)*2, i11 = (ly1*WX + lx1)*2;
                #pragma unroll
                for (int v = 0; v < 2; v++) {
                    float4 a00 = w4[i00 + v];
                    float4 a01 = w4[i01 + v];
                    float4 a10 = w4[i10 + v];
                    float4 a11 = w4[i11 + v];
                    const ull* p00 = (const ull*)&a00;
                    const ull* p01 = (const ull*)&a01;
                    const ull* p10 = (const ull*)&a10;
                    const ull* p11 = (const ull*)&a11;
                    #pragma unroll
                    for (int hh = 0; hh < 2; hh++) {
                        ull acc = yac2[v*2+hh];
                        acc = ffma2(W00, p00[hh], acc);
                        acc = ffma2(W01, p01[hh], acc);
                        acc = ffma2(W10, p10[hh], acc);
                        acc = ffma2(W11, p11[hh], acc);
                        yac2[v*2+hh] = acc;
                    }
                }
            }
            float* yp = y + (((size_t)b*32 + qtr*8)*256 + gy)*256 + gx;
            const float* yf = (const float*)yac2;
            #pragma unroll
            for (int c = 0; c < 8; c++) yp[c*65536] = yf[c];
            #pragma unroll
            for (int c = 0; c < 8; c++) {
                float v = yf[c];
                v += __shfl_down_sync(0xffffffffu, v, 16);
                v += __shfl_down_sync(0xffffffffu, v, 8);
                v += __shfl_down_sync(0xffffffffu, v, 4);
                v += __shfl_down_sync(0xffffffffu, v, 2);
                v += __shfl_down_sync(0xffffffffu, v, 1);
                if (lane == 0) s_cs[(qtr*8+c)*8 + wid] += v;
            }
        }
    }

    __syncthreads();
    if (tid < 32) {
        float s = 0.f;
        #pragma unroll
        for (int w = 0; w < 8; w++) s += s_cs[tid*8 + w];
        py[(b*128 + blkLocal)*32 + tid] = s;
    }
}

// alpha math, run by last head block
__device__ void alpha_tail(const float* pz0, const float* py1, const float* py2,
                           const float* rw1, const float* rb1,
                           const float* rw2, const float* rb2,
                           float* alpha, float* sm, int tid)
{
    float* s_cat = sm;          // 384
    float* s_hid = sm + 384;    // 128
    float* s_lg  = sm + 512;    // 12
    if (tid < 128) {
        int b = tid >> 5, c = tid & 31;
        float s0 = 0.f;
        #pragma unroll 8
        for (int k = 0; k < 256; k++) s0 += pz0[((b<<8)+k)*32 + c];
        float s1 = 0.f;
        #pragma unroll 8
        for (int k = 0; k < 128; k++) s1 += py1[((b<<7)+k)*32 + c];
        float s2 = 0.f;
        #pragma unroll 8
        for (int k = 0; k < 128; k++) s2 += py2[((b<<7)+k)*32 + c];
        const float inv = 1.0f/65536.0f;
        s_cat[b*96 +      c] = s0*inv;
        s_cat[b*96 + 32 + c] = s1*inv;
        s_cat[b*96 + 64 + c] = s2*inv;
    }
    __syncthreads();
    if (tid < 128) {
        int b = tid >> 5, c = tid & 31;
        float a = rb1[c];
        const float* cat = s_cat + b*96;
        #pragma unroll 8
        for (int j = 0; j < 96; j++) a += cat[j]*rw1[j*32 + c];
        s_hid[b*32 + c] = a / (1.f + __expf(-a));
    }
    __syncthreads();
    if (tid < 12) {
        int bb = tid / 3, t2 = tid % 3;
        float a = rb2[t2];
        #pragma unroll
        for (int o = 0; o < 32; o++) a += s_hid[bb*32+o]*rw2[o*3+t2];
        s_lg[bb*3+t2] = a;
    }
    __syncthreads();
    if (tid < 4) {
        float l0 = s_lg[tid*3], l1 = s_lg[tid*3+1], l2 = s_lg[tid*3+2];
        float m = fmaxf(l0, fmaxf(l1, l2));
        float e0 = __expf(l0-m), e1 = __expf(l1-m), e2 = __expf(l2-m);
        float inv = 1.f/(e0+e1+e2);
        alpha[tid*3+0] = e0*inv; alpha[tid*3+1] = e1*inv; alpha[tid*3+2] = e2*inv;
    }
}

__global__ void __launch_bounds__(256, 3) head_fat_kernel(
    const float* __restrict__ q,
    const float* __restrict__ z1, const float* __restrict__ z2,
    const float* h1w1, const float* h1w2, const float* h1b2,
    const float* h2w1, const float* h2w2, const float* h2b2,
    float* y1, float* y2, float* py1, float* py2,
    const float* pz0,
    const float* rw1, const float* rb1, const float* rw2, const float* rb2,
    float* alpha)
{
    __shared__ __align__(16) float smem[7056];
    __shared__ int s_last;
    int hb = blockIdx.x;
    int tid = threadIdx.x;
    if (hb < 512) {
        int local = hb & 127;
        head_impl<128,128,40,10>(smem, q, z1, h1w1, h1w2, h1b2, y1, py1,
                                 local & 3, local >> 2, hb >> 7, local);
    } else {
        int r = hb - 512;
        int local = r & 127;
        head_impl<64,64,24,8>(smem, q, z2, h2w1, h2w2, h2b2, y2, py2,
                              local & 3, local >> 2, r >> 7, local);
    }
    __syncthreads();
    if (tid == 0) {
        __threadfence();
        int old = atomicAdd(&g_ctr, 1);
        s_last = (old == (int)gridDim.x - 1) ? 1 : 0;
    }
    __syncthreads();
    if (s_last) {
        if (tid == 0) { g_ctr = 0; __threadfence(); }
        alpha_tail(pz0, py1, py2, rw1, rb1, rw2, rb2, alpha, smem, tid);
    }
}

// ---------------- final: alpha-mix + 1x1 conv (f32x2) + residual; all CHW ----------------
__global__ void __launch_bounds__(256, 4) final_kernel(
                             const float* __restrict__ x,
                             const float* __restrict__ z0,
                             const float* __restrict__ y1,
                             const float* __restrict__ y2,
                             const float* __restrict__ fw,
                             const float* __restrict__ alpha,
                             float* __restrict__ out)
{
    __shared__ __align__(16) float s_fwT[1024];   // [c][o]
    for (int i = threadIdx.x; i < 1024; i += 256) {
        int o = i >> 5, c = i & 31;
        s_fwT[c*32 + o] = fw[i];
    }
    __syncthreads();
    int b = blockIdx.y;
    int pix = blockIdx.x*256 + threadIdx.x;
    float a0 = alpha[b*3], a1 = alpha[b*3+1], a2 = alpha[b*3+2];
    size_t base = (size_t)b*32*65536 + pix;

    ull acc2[16];
    #pragma unroll
    for (int op = 0; op < 16; op++) acc2[op] = 0ull;

    #pragma unroll
    for (int c = 0; c < 32; c++) {
        size_t idx = base + (size_t)c*65536;
        float mval = a0*z0[idx] + a1*y1[idx] + a2*y2[idx];
        ull m2 = pack2(mval, mval);
        const float4* wrow = (const float4*)(s_fwT + c*32);
        #pragma unroll
        for (int oq = 0; oq < 8; oq++) {
            float4 w4 = wrow[oq];
            const ull* wp = (const ull*)&w4;
            acc2[oq*2+0] = ffma2(m2, wp[0], acc2[oq*2+0]);
            acc2[oq*2+1] = ffma2(m2, wp[1], acc2[oq*2+1]);
        }
    }
    #pragma unroll
    for (int op = 0; op < 16; op++) {
        float2 f = unpack2(acc2[op]);
        size_t i0 = base + (size_t)(2*op)*65536;
        size_t i1 = base + (size_t)(2*op+1)*65536;
        out[i0] = x[i0] + f.x;
        out[i1] = x[i1] + f.y;
    }
}

// ---------------- launch ----------------
extern "C" void kernel_launch(void* const* d_in, const int* in_sizes, int n_in,
                              void* d_out, int out_size)
{
    const float* x       = (const float*)d_in[0];
    const float* ds0_dw  = (const float*)d_in[1];
    const float* ds0_pw  = (const float*)d_in[2];
    const float* ds0_g   = (const float*)d_in[3];
    const float* ds0_b   = (const float*)d_in[4];
    const float* ds0_m   = (const float*)d_in[5];
    const float* ds0_v   = (const float*)d_in[6];
    const float* ds1_dw  = (const float*)d_in[7];
    const float* ds1_pw  = (const float*)d_in[8];
    const float* ds1_g   = (const float*)d_in[9];
    const float* ds1_b   = (const float*)d_in[10];
    const float* ds1_m   = (const float*)d_in[11];
    const float* ds1_v   = (const float*)d_in[12];
    const float* ds2_dw  = (const float*)d_in[13];
    const float* ds2_pw  = (const float*)d_in[14];
    const float* ds2_g   = (const float*)d_in[15];
    const float* ds2_b   = (const float*)d_in[16];
    const float* ds2_m   = (const float*)d_in[17];
    const float* ds2_v   = (const float*)d_in[18];
    const float* qproj_w = (const float*)d_in[19];
    const float* h1_w1   = (const float*)d_in[20];
    const float* h1_w2   = (const float*)d_in[21];
    const float* h1_b2   = (const float*)d_in[22];
    const float* h2_w1   = (const float*)d_in[23];
    const float* h2_w2   = (const float*)d_in[24];
    const float* h2_b2   = (const float*)d_in[25];
    const float* r_w1    = (const float*)d_in[26];
    const float* r_b1    = (const float*)d_in[27];
    const float* r_w2    = (const float*)d_in[28];
    const float* r_b2    = (const float*)d_in[29];
    const float* final_w = (const float*)d_in[30];
    float* out = (float*)d_out;

    float *z0, *q, *z1, *z2, *y1, *y2, *pz0, *py1, *py2, *alpha;
    cudaGetSymbolAddress((void**)&z0,    g_z0);
    cudaGetSymbolAddress((void**)&q,     g_q);
    cudaGetSymbolAddress((void**)&z1,    g_z1);
    cudaGetSymbolAddress((void**)&z2,    g_z2);
    cudaGetSymbolAddress((void**)&y1,    g_y1);
    cudaGetSymbolAddress((void**)&y2,    g_y2);
    cudaGetSymbolAddress((void**)&pz0,   g_pz0);
    cudaGetSymbolAddress((void**)&py1,   g_py1);
    cudaGetSymbolAddress((void**)&py2,   g_py2);
    cudaGetSymbolAddress((void**)&alpha, g_alpha);

    ds_fat_kernel<<<1344, 256>>>(x,
        ds0_dw, ds0_pw, ds0_g, ds0_b, ds0_m, ds0_v,
        ds1_dw, ds1_pw, ds1_g, ds1_b, ds1_m, ds1_v,
        ds2_dw, ds2_pw, ds2_g, ds2_b, ds2_m, ds2_v,
        qproj_w, z0, q, z1, z2, pz0);

    head_fat_kernel<<<1024, 256>>>(q, z1, z2,
        h1_w1, h1_w2, h1_b2, h2_w1, h2_w2, h2_b2, y1, y2, py1, py2,
        pz0, r_w1, r_b1, r_w2, r_b2, alpha);

    final_kernel<<<dim3(256,4), 256>>>(x, z0, y1, y2, final_w, alpha, out);
}